// round 1
// baseline (speedup 1.0000x reference)
#include <cuda_runtime.h>

// Problem dims
#define B_  4
#define S_  2048
#define E_  768
#define H_  3
#define D_  256
#define BS_ (B_ * S_)   // 8192

// Scratch (device globals — no allocation allowed)
__device__ float g_Q[(size_t)B_ * H_ * S_ * D_];   // 25.2 MB
__device__ float g_K[(size_t)B_ * H_ * S_ * D_];
__device__ float g_V[(size_t)B_ * H_ * S_ * D_];
__device__ float g_Sc[(size_t)B_ * H_ * S_ * S_];  // 201 MB (scores -> probs, in place)
__device__ float g_C[(size_t)B_ * S_ * E_];        // concat heads

// ---------------------------------------------------------------------------
// Kernel 1: per-head projections  Out[b,h,s,d] = sum_e X[b,s,e] * W[h,e,d]
// grid: (D/64=4, BS/64=128, 3 tensors * 3 heads = 9), block 256
// ---------------------------------------------------------------------------
__global__ __launch_bounds__(256) void proj_kernel(
    const float* __restrict__ Xk, const float* __restrict__ Xv, const float* __restrict__ Xq,
    const float* __restrict__ WK, const float* __restrict__ WV, const float* __restrict__ WQ)
{
    int h = blockIdx.z % H_;
    int t = blockIdx.z / H_;
    const float* X = (t == 0) ? Xk : (t == 1) ? Xv : Xq;
    const float* W = ((t == 0) ? WK : (t == 1) ? WV : WQ) + (size_t)h * E_ * D_;
    float* Out     = (t == 0) ? g_K : (t == 1) ? g_V : g_Q;

    int m0 = blockIdx.y * 64;
    int n0 = blockIdx.x * 64;

    __shared__ float As[64][17];
    __shared__ float Bs[16][64];

    int tid = threadIdx.x;
    int tx = tid & 15, ty = tid >> 4;
    float acc[4][4] = {};

    for (int k0 = 0; k0 < E_; k0 += 16) {
        #pragma unroll
        for (int i = 0; i < 4; i++) {
            int idx = tid + i * 256;
            int r = idx >> 4, kk = idx & 15;
            As[r][kk] = X[(size_t)(m0 + r) * E_ + k0 + kk];
        }
        #pragma unroll
        for (int i = 0; i < 4; i++) {
            int idx = tid + i * 256;
            int kk = idx >> 6, c = idx & 63;
            Bs[kk][c] = W[(size_t)(k0 + kk) * D_ + n0 + c];
        }
        __syncthreads();
        #pragma unroll
        for (int kk = 0; kk < 16; kk++) {
            float a[4];
            #pragma unroll
            for (int i = 0; i < 4; i++) a[i] = As[ty * 4 + i][kk];
            float4 bv = *(const float4*)&Bs[kk][tx * 4];
            float b[4] = {bv.x, bv.y, bv.z, bv.w};
            #pragma unroll
            for (int i = 0; i < 4; i++)
                #pragma unroll
                for (int j = 0; j < 4; j++) acc[i][j] += a[i] * b[j];
        }
        __syncthreads();
    }

    #pragma unroll
    for (int i = 0; i < 4; i++) {
        int m = m0 + ty * 4 + i;
        int bb = m >> 11;             // m / S_
        int ss = m & (S_ - 1);
        float* o = Out + (((size_t)(bb * H_ + h) * S_ + ss) * D_ + n0 + tx * 4);
        o[0] = acc[i][0]; o[1] = acc[i][1]; o[2] = acc[i][2]; o[3] = acc[i][3];
    }
}

// ---------------------------------------------------------------------------
// Kernel 2: scores  Sc[q,k] = (Q[q,:] . K[k,:]) / sqrt(S)   (lower tiles only)
// grid: (32 kt, 32 qt, 12 bh), block 256
// ---------------------------------------------------------------------------
__global__ __launch_bounds__(256) void scores_kernel()
{
    int kt = blockIdx.x, qt = blockIdx.y, bh = blockIdx.z;
    if (kt > qt) return;

    const float* Q  = g_Q + (size_t)bh * S_ * D_;
    const float* K  = g_K + (size_t)bh * S_ * D_;
    float*       Sc = g_Sc + (size_t)bh * S_ * S_;

    int q0 = qt * 64, k0c = kt * 64;

    __shared__ float As[64][17];   // [q][d]
    __shared__ float Bs[16][65];   // [d][k]

    int tid = threadIdx.x;
    int tx = tid & 15, ty = tid >> 4;
    float acc[4][4] = {};

    for (int d0 = 0; d0 < D_; d0 += 16) {
        #pragma unroll
        for (int i = 0; i < 4; i++) {
            int idx = tid + i * 256;
            int r = idx >> 4, kk = idx & 15;
            As[r][kk] = Q[(size_t)(q0 + r) * D_ + d0 + kk];
        }
        #pragma unroll
        for (int i = 0; i < 4; i++) {
            int idx = tid + i * 256;
            int c = idx >> 4, kk = idx & 15;
            Bs[kk][c] = K[(size_t)(k0c + c) * D_ + d0 + kk];
        }
        __syncthreads();
        #pragma unroll
        for (int kk = 0; kk < 16; kk++) {
            float a[4], b[4];
            #pragma unroll
            for (int i = 0; i < 4; i++) a[i] = As[ty * 4 + i][kk];
            #pragma unroll
            for (int j = 0; j < 4; j++) b[j] = Bs[kk][tx * 4 + j];
            #pragma unroll
            for (int i = 0; i < 4; i++)
                #pragma unroll
                for (int j = 0; j < 4; j++) acc[i][j] += a[i] * b[j];
        }
        __syncthreads();
    }

    const float scale = 0.022097086912079612f;  // 1/sqrt(2048)
    #pragma unroll
    for (int i = 0; i < 4; i++) {
        float* o = Sc + (size_t)(q0 + ty * 4 + i) * S_ + k0c + tx * 4;
        #pragma unroll
        for (int j = 0; j < 4; j++) o[j] = acc[i][j] * scale;
    }
}

// ---------------------------------------------------------------------------
// Kernel 3: causal softmax per row (reads k<=q, zero-fills k>q)
// grid: B*H*S = 24576 blocks, 256 threads
// ---------------------------------------------------------------------------
__global__ __launch_bounds__(256) void softmax_kernel()
{
    int row = blockIdx.x;
    int q = row & (S_ - 1);
    float* p = g_Sc + (size_t)row * S_;

    __shared__ float red[256];
    int tid = threadIdx.x;

    float m = -1e30f;
    for (int k = tid; k <= q; k += 256) m = fmaxf(m, p[k]);
    red[tid] = m; __syncthreads();
    for (int s = 128; s > 0; s >>= 1) {
        if (tid < s) red[tid] = fmaxf(red[tid], red[tid + s]);
        __syncthreads();
    }
    m = red[0]; __syncthreads();

    float sum = 0.f;
    for (int k = tid; k <= q; k += 256) sum += __expf(p[k] - m);
    red[tid] = sum; __syncthreads();
    for (int s = 128; s > 0; s >>= 1) {
        if (tid < s) red[tid] += red[tid + s];
        __syncthreads();
    }
    float inv = 1.0f / red[0];

    for (int k = tid; k <= q; k += 256) p[k] = __expf(p[k] - m) * inv;
    for (int k = q + 1 + tid; k < S_; k += 256) p[k] = 0.f;
}

// ---------------------------------------------------------------------------
// Kernel 4: Z = P @ V, written directly in concat layout g_C[b, q, h*D + d]
// grid: (4 nt, 32 qt, 12 bh), block 256
// ---------------------------------------------------------------------------
__global__ __launch_bounds__(256) void pv_kernel()
{
    int nt = blockIdx.x, qt = blockIdx.y, bh = blockIdx.z;
    const float* P = g_Sc + (size_t)bh * S_ * S_;
    const float* V = g_V + (size_t)bh * S_ * D_;

    int q0 = qt * 64, n0 = nt * 64;
    int kmax = (qt + 1) * 64;   // P is zero beyond the diagonal

    __shared__ float As[64][17];
    __shared__ float Bs[16][64];

    int tid = threadIdx.x;
    int tx = tid & 15, ty = tid >> 4;
    float acc[4][4] = {};

    for (int k0 = 0; k0 < kmax; k0 += 16) {
        #pragma unroll
        for (int i = 0; i < 4; i++) {
            int idx = tid + i * 256;
            int r = idx >> 4, kk = idx & 15;
            As[r][kk] = P[(size_t)(q0 + r) * S_ + k0 + kk];
        }
        #pragma unroll
        for (int i = 0; i < 4; i++) {
            int idx = tid + i * 256;
            int kk = idx >> 6, c = idx & 63;
            Bs[kk][c] = V[(size_t)(k0 + kk) * D_ + n0 + c];
        }
        __syncthreads();
        #pragma unroll
        for (int kk = 0; kk < 16; kk++) {
            float a[4];
            #pragma unroll
            for (int i = 0; i < 4; i++) a[i] = As[ty * 4 + i][kk];
            float4 bv = *(const float4*)&Bs[kk][tx * 4];
            float b[4] = {bv.x, bv.y, bv.z, bv.w};
            #pragma unroll
            for (int i = 0; i < 4; i++)
                #pragma unroll
                for (int j = 0; j < 4; j++) acc[i][j] += a[i] * b[j];
        }
        __syncthreads();
    }

    int bb = bh / H_, h = bh - bb * H_;
    #pragma unroll
    for (int i = 0; i < 4; i++) {
        int q = q0 + ty * 4 + i;
        float* o = g_C + ((size_t)(bb * S_ + q) * E_ + h * D_ + n0 + tx * 4);
        o[0] = acc[i][0]; o[1] = acc[i][1]; o[2] = acc[i][2]; o[3] = acc[i][3];
    }
}

// ---------------------------------------------------------------------------
// Kernel 5: Out = g_C @ Wo + bo    (8192 x 768 x 768)
// grid: (12 nt, 128 mt), block 256
// ---------------------------------------------------------------------------
__global__ __launch_bounds__(256) void out_kernel(
    const float* __restrict__ Wo, const float* __restrict__ bo, float* __restrict__ Out)
{
    int n0 = blockIdx.x * 64;
    int m0 = blockIdx.y * 64;

    __shared__ float As[64][17];
    __shared__ float Bs[16][64];

    int tid = threadIdx.x;
    int tx = tid & 15, ty = tid >> 4;
    float acc[4][4] = {};

    for (int k0 = 0; k0 < E_; k0 += 16) {
        #pragma unroll
        for (int i = 0; i < 4; i++) {
            int idx = tid + i * 256;
            int r = idx >> 4, kk = idx & 15;
            As[r][kk] = g_C[(size_t)(m0 + r) * E_ + k0 + kk];
        }
        #pragma unroll
        for (int i = 0; i < 4; i++) {
            int idx = tid + i * 256;
            int kk = idx >> 6, c = idx & 63;
            Bs[kk][c] = Wo[(size_t)(k0 + kk) * E_ + n0 + c];
        }
        __syncthreads();
        #pragma unroll
        for (int kk = 0; kk < 16; kk++) {
            float a[4];
            #pragma unroll
            for (int i = 0; i < 4; i++) a[i] = As[ty * 4 + i][kk];
            float4 bv = *(const float4*)&Bs[kk][tx * 4];
            float b[4] = {bv.x, bv.y, bv.z, bv.w};
            #pragma unroll
            for (int i = 0; i < 4; i++)
                #pragma unroll
                for (int j = 0; j < 4; j++) acc[i][j] += a[i] * b[j];
        }
        __syncthreads();
    }

    #pragma unroll
    for (int i = 0; i < 4; i++) {
        int m = m0 + ty * 4 + i;
        float* o = Out + (size_t)m * E_ + n0 + tx * 4;
        #pragma unroll
        for (int j = 0; j < 4; j++) o[j] = acc[i][j] + bo[n0 + tx * 4 + j];
    }
}

// ---------------------------------------------------------------------------
extern "C" void kernel_launch(void* const* d_in, const int* in_sizes, int n_in,
                              void* d_out, int out_size)
{
    const float* Xk = (const float*)d_in[0];
    const float* Xv = (const float*)d_in[1];
    const float* Xq = (const float*)d_in[2];
    const float* WK = (const float*)d_in[3];
    const float* WV = (const float*)d_in[4];
    const float* WQ = (const float*)d_in[5];
    const float* Wo = (const float*)d_in[6];
    const float* bo = (const float*)d_in[7];
    float* out = (float*)d_out;

    proj_kernel<<<dim3(4, 128, 9), 256>>>(Xk, Xv, Xq, WK, WV, WQ);
    scores_kernel<<<dim3(32, 32, 12), 256>>>();
    softmax_kernel<<<dim3(B_ * H_ * S_), 256>>>();
    pv_kernel<<<dim3(4, 32, 12), 256>>>();
    out_kernel<<<dim3(12, 128), 256>>>(Wo, bo, out);
}

// round 3
// speedup vs baseline: 2.8629x; 2.8629x over previous
#include <cuda_runtime.h>
#include <cstdint>

#define B_  4
#define S_  2048
#define E_  768
#define H_  3
#define D_  256

#define BK  16
#define PA  20     // A smem row pitch (floats)
#define PB  136    // B smem row pitch (floats)

// Scratch (device globals — no allocation allowed)
__device__ float g_Q[(size_t)B_ * H_ * S_ * D_];
__device__ float g_K[(size_t)B_ * H_ * S_ * D_];
__device__ float g_V[(size_t)B_ * H_ * S_ * D_];
__device__ float g_Sc[(size_t)B_ * H_ * S_ * S_];  // scores -> probs in place
__device__ float g_C[(size_t)B_ * S_ * E_];        // concat heads

// ---------------------------------------------------------------------------
__device__ __forceinline__ float f2tf(float f) {
    uint32_t u;
    asm("cvt.rna.tf32.f32 %0, %1;" : "=r"(u) : "f"(f));
    return __uint_as_float(u);
}
__device__ __forceinline__ float4 cvt4(float4 v) {
    return make_float4(f2tf(v.x), f2tf(v.y), f2tf(v.z), f2tf(v.w));
}
__device__ __forceinline__ void mma8(float c[4], const uint32_t a[4], const uint32_t b[2]) {
    asm volatile("mma.sync.aligned.m16n8k8.row.col.f32.tf32.tf32.f32 "
        "{%0,%1,%2,%3}, {%4,%5,%6,%7}, {%8,%9}, {%0,%1,%2,%3};"
        : "+f"(c[0]), "+f"(c[1]), "+f"(c[2]), "+f"(c[3])
        : "r"(a[0]), "r"(a[1]), "r"(a[2]), "r"(a[3]), "r"(b[0]), "r"(b[1]));
}

// ---------------------------------------------------------------------------
// 128x128 tile GEMM: acc += A[128,Ktot] * B^T.
// TRANSB=1: Bp is [K,N] row-major (n contiguous)  -> direct store.
// TRANSB=0: Bp is [N,K] row-major (k contiguous)  -> transpose at store.
// ---------------------------------------------------------------------------
template<int TRANSB>
__device__ __forceinline__ void gemm_tile(
    float acc[4][4][4],
    const float* __restrict__ A, int lda,
    const float* __restrict__ Bp, int ldb, int Ktot,
    float* sA, float* sB)
{
    int tid = threadIdx.x, lane = tid & 31, wid = tid >> 5;
    int wm = (wid & 1) * 64, wn = (wid >> 1) * 32;

    for (int k0 = 0; k0 < Ktot; k0 += BK) {
        // A tile: 128 rows x 16 k  (each thread: 2 float4)
        #pragma unroll
        for (int i = 0; i < 2; i++) {
            int f = tid + i * 256;
            int row = f >> 2, q = f & 3;
            float4 v = cvt4(*(const float4*)(A + (size_t)row * lda + k0 + q * 4));
            *(float4*)(sA + row * PA + q * 4) = v;
        }
        // B tile: 16 k x 128 n
        if (TRANSB == 1) {
            #pragma unroll
            for (int i = 0; i < 2; i++) {
                int f = tid + i * 256;
                int k = f >> 5, n4 = f & 31;
                float4 v = cvt4(*(const float4*)(Bp + (size_t)(k0 + k) * ldb + n4 * 4));
                *(float4*)(sB + k * PB + n4 * 4) = v;
            }
        } else {
            #pragma unroll
            for (int i = 0; i < 2; i++) {
                int f = tid + i * 256;
                int n = f >> 2, q = f & 3;
                float4 v = cvt4(*(const float4*)(Bp + (size_t)n * ldb + k0 + q * 4));
                sB[(q * 4 + 0) * PB + n] = v.x;
                sB[(q * 4 + 1) * PB + n] = v.y;
                sB[(q * 4 + 2) * PB + n] = v.z;
                sB[(q * 4 + 3) * PB + n] = v.w;
            }
        }
        __syncthreads();

        #pragma unroll
        for (int ks = 0; ks < BK; ks += 8) {
            uint32_t a[4][4];
            #pragma unroll
            for (int mf = 0; mf < 4; mf++) {
                int r = wm + mf * 16 + (lane >> 2);
                int c = ks + (lane & 3);
                a[mf][0] = __float_as_uint(sA[r * PA + c]);
                a[mf][1] = __float_as_uint(sA[(r + 8) * PA + c]);
                a[mf][2] = __float_as_uint(sA[r * PA + c + 4]);
                a[mf][3] = __float_as_uint(sA[(r + 8) * PA + c + 4]);
            }
            uint32_t b[4][2];
            #pragma unroll
            for (int nf = 0; nf < 4; nf++) {
                int kk = ks + (lane & 3);
                int n  = wn + nf * 8 + (lane >> 2);
                b[nf][0] = __float_as_uint(sB[kk * PB + n]);
                b[nf][1] = __float_as_uint(sB[(kk + 4) * PB + n]);
            }
            #pragma unroll
            for (int mf = 0; mf < 4; mf++)
                #pragma unroll
                for (int nf = 0; nf < 4; nf++)
                    mma8(acc[mf][nf], a[mf], b[nf]);
        }
        __syncthreads();
    }
}

// ---------------------------------------------------------------------------
// Kernel 1: projections  Out[b,h,s,d] = X[b,s,:] @ W[h,:,:]
// grid (2 nt, 64 mt, 9 = tensor*3 + head)
// ---------------------------------------------------------------------------
__global__ __launch_bounds__(256) void proj_tc(
    const float* __restrict__ Xk, const float* __restrict__ Xv, const float* __restrict__ Xq,
    const float* __restrict__ WK, const float* __restrict__ WV, const float* __restrict__ WQ)
{
    __shared__ float sA[128 * PA];
    __shared__ float sB[BK * PB];
    int z = blockIdx.z;
    int t = z / 3, h = z % 3;
    const float* X = (t == 0) ? Xk : (t == 1) ? Xv : Xq;
    const float* W = ((t == 0) ? WK : (t == 1) ? WV : WQ) + (size_t)h * E_ * D_;
    float* Out     = (t == 0) ? g_K : (t == 1) ? g_V : g_Q;

    int m0 = blockIdx.y * 128, n0 = blockIdx.x * 128;
    float acc[4][4][4] = {};
    gemm_tile<1>(acc, X + (size_t)m0 * E_, E_, W + n0, D_, E_, sA, sB);

    int lane = threadIdx.x & 31, wid = threadIdx.x >> 5;
    int wm = (wid & 1) * 64, wn = (wid >> 1) * 32;
    #pragma unroll
    for (int mf = 0; mf < 4; mf++) {
        #pragma unroll
        for (int half = 0; half < 2; half++) {
            int m = m0 + wm + mf * 16 + (lane >> 2) + half * 8;
            int bb = m >> 11, ss = m & (S_ - 1);
            float* orow = Out + (((size_t)(bb * H_ + h)) * S_ + ss) * D_ + n0;
            #pragma unroll
            for (int nf = 0; nf < 4; nf++) {
                int col = wn + nf * 8 + 2 * (lane & 3);
                float2 v = half ? make_float2(acc[mf][nf][2], acc[mf][nf][3])
                                : make_float2(acc[mf][nf][0], acc[mf][nf][1]);
                *(float2*)(orow + col) = v;
            }
        }
    }
}

// ---------------------------------------------------------------------------
// Kernel 2: scores  Sc[q,k] = Q[q,:].K[k,:] / sqrt(S)   (lower tiles only)
// grid (16 kt, 16 qt, 12 bh)
// ---------------------------------------------------------------------------
__global__ __launch_bounds__(256) void scores_tc()
{
    int kt = blockIdx.x, qt = blockIdx.y, bh = blockIdx.z;
    if (kt > qt) return;
    __shared__ float sA[128 * PA];
    __shared__ float sB[BK * PB];

    int q0 = qt * 128, k0 = kt * 128;
    const float* Q = g_Q + (size_t)bh * S_ * D_ + (size_t)q0 * D_;
    const float* K = g_K + (size_t)bh * S_ * D_ + (size_t)k0 * D_;
    float acc[4][4][4] = {};
    gemm_tile<0>(acc, Q, D_, K, D_, D_, sA, sB);

    const float scale = 0.022097086912079612f;  // 1/sqrt(2048)
    int lane = threadIdx.x & 31, wid = threadIdx.x >> 5;
    int wm = (wid & 1) * 64, wn = (wid >> 1) * 32;
    float* Sc = g_Sc + (size_t)bh * S_ * S_;
    #pragma unroll
    for (int mf = 0; mf < 4; mf++) {
        #pragma unroll
        for (int half = 0; half < 2; half++) {
            int q = q0 + wm + mf * 16 + (lane >> 2) + half * 8;
            float* orow = Sc + (size_t)q * S_ + k0;
            #pragma unroll
            for (int nf = 0; nf < 4; nf++) {
                int col = wn + nf * 8 + 2 * (lane & 3);
                float2 v = half ? make_float2(acc[mf][nf][2] * scale, acc[mf][nf][3] * scale)
                                : make_float2(acc[mf][nf][0] * scale, acc[mf][nf][1] * scale);
                *(float2*)(orow + col) = v;
            }
        }
    }
}

// ---------------------------------------------------------------------------
// Kernel 3: causal softmax per row
// ---------------------------------------------------------------------------
__global__ __launch_bounds__(256) void softmax_kernel()
{
    int row = blockIdx.x;
    int q = row & (S_ - 1);
    float* p = g_Sc + (size_t)row * S_;

    __shared__ float red[256];
    int tid = threadIdx.x;

    float m = -1e30f;
    for (int k = tid; k <= q; k += 256) m = fmaxf(m, p[k]);
    red[tid] = m; __syncthreads();
    for (int s = 128; s > 0; s >>= 1) {
        if (tid < s) red[tid] = fmaxf(red[tid], red[tid + s]);
        __syncthreads();
    }
    m = red[0]; __syncthreads();

    float sum = 0.f;
    for (int k = tid; k <= q; k += 256) sum += __expf(p[k] - m);
    red[tid] = sum; __syncthreads();
    for (int s = 128; s > 0; s >>= 1) {
        if (tid < s) red[tid] += red[tid + s];
        __syncthreads();
    }
    float inv = 1.0f / red[0];

    for (int k = tid; k <= q; k += 256) p[k] = __expf(p[k] - m) * inv;
    for (int k = q + 1 + tid; k < S_; k += 256) p[k] = 0.f;
}

// ---------------------------------------------------------------------------
// Kernel 4: Z = P @ V  -> concat layout g_C[b, q, h*D+d]
// grid (2 nt, 16 qt, 12 bh); K truncated at diagonal (P zero beyond)
// ---------------------------------------------------------------------------
__global__ __launch_bounds__(256) void pv_tc()
{
    int nt = blockIdx.x, qt = blockIdx.y, bh = blockIdx.z;
    __shared__ float sA[128 * PA];
    __shared__ float sB[BK * PB];

    int q0 = qt * 128, n0 = nt * 128;
    const float* P = g_Sc + (size_t)bh * S_ * S_ + (size_t)q0 * S_;
    const float* V = g_V + (size_t)bh * S_ * D_ + n0;
    float acc[4][4][4] = {};
    gemm_tile<1>(acc, P, S_, V, D_, (qt + 1) * 128, sA, sB);

    int lane = threadIdx.x & 31, wid = threadIdx.x >> 5;
    int wm = (wid & 1) * 64, wn = (wid >> 1) * 32;
    int bb = bh / H_, h = bh - bb * H_;
    #pragma unroll
    for (int mf = 0; mf < 4; mf++) {
        #pragma unroll
        for (int half = 0; half < 2; half++) {
            int q = q0 + wm + mf * 16 + (lane >> 2) + half * 8;
            float* orow = g_C + ((size_t)(bb * S_ + q)) * E_ + h * D_ + n0;
            #pragma unroll
            for (int nf = 0; nf < 4; nf++) {
                int col = wn + nf * 8 + 2 * (lane & 3);
                float2 v = half ? make_float2(acc[mf][nf][2], acc[mf][nf][3])
                                : make_float2(acc[mf][nf][0], acc[mf][nf][1]);
                *(float2*)(orow + col) = v;
            }
        }
    }
}

// ---------------------------------------------------------------------------
// Kernel 5: Out = g_C @ Wo + bo   grid (6 nt, 64 mt)
// ---------------------------------------------------------------------------
__global__ __launch_bounds__(256) void out_tc(
    const float* __restrict__ Wo, const float* __restrict__ bo, float* __restrict__ Out)
{
    __shared__ float sA[128 * PA];
    __shared__ float sB[BK * PB];
    int n0 = blockIdx.x * 128, m0 = blockIdx.y * 128;
    float acc[4][4][4] = {};
    gemm_tile<1>(acc, g_C + (size_t)m0 * E_, E_, Wo + n0, E_, E_, sA, sB);

    int lane = threadIdx.x & 31, wid = threadIdx.x >> 5;
    int wm = (wid & 1) * 64, wn = (wid >> 1) * 32;
    #pragma unroll
    for (int mf = 0; mf < 4; mf++) {
        #pragma unroll
        for (int half = 0; half < 2; half++) {
            int m = m0 + wm + mf * 16 + (lane >> 2) + half * 8;
            float* orow = Out + (size_t)m * E_ + n0;
            #pragma unroll
            for (int nf = 0; nf < 4; nf++) {
                int col = wn + nf * 8 + 2 * (lane & 3);
                float2 bv = *(const float2*)(bo + n0 + col);
                float2 v = half ? make_float2(acc[mf][nf][2] + bv.x, acc[mf][nf][3] + bv.y)
                                : make_float2(acc[mf][nf][0] + bv.x, acc[mf][nf][1] + bv.y);
                *(float2*)(orow + col) = v;
            }
        }
    }
}

// ---------------------------------------------------------------------------
extern "C" void kernel_launch(void* const* d_in, const int* in_sizes, int n_in,
                              void* d_out, int out_size)
{
    const float* Xk = (const float*)d_in[0];
    const float* Xv = (const float*)d_in[1];
    const float* Xq = (const float*)d_in[2];
    const float* WK = (const float*)d_in[3];
    const float* WV = (const float*)d_in[4];
    const float* WQ = (const float*)d_in[5];
    const float* Wo = (const float*)d_in[6];
    const float* bo = (const float*)d_in[7];
    float* out = (float*)d_out;

    proj_tc<<<dim3(2, 64, 9), 256>>>(Xk, Xv, Xq, WK, WV, WQ);
    scores_tc<<<dim3(16, 16, 12), 256>>>();
    softmax_kernel<<<dim3(B_ * H_ * S_), 256>>>();
    pv_tc<<<dim3(2, 16, 12), 256>>>();
    out_tc<<<dim3(6, 64), 256>>>(Wo, bo, out);
}

// round 4
// speedup vs baseline: 3.7965x; 1.3261x over previous
#include <cuda_runtime.h>
#include <cstdint>

#define B_  4
#define S_  2048
#define E_  768
#define H_  3
#define D_  256

#define BK  16
#define PA  20     // A smem row pitch (floats) — (20r+c)%32 conflict-free frag reads
#define PB  136    // B smem row pitch (floats) — (136k+n)%32 = (8k+n)%32 conflict-free

// Scratch (device globals — no allocation allowed)
__device__ float g_Q[(size_t)B_ * H_ * S_ * D_];
__device__ float g_K[(size_t)B_ * H_ * S_ * D_];
__device__ float g_V[(size_t)B_ * H_ * S_ * D_];
__device__ float g_Sc[(size_t)B_ * H_ * S_ * S_];  // scores -> probs in place
__device__ float g_C[(size_t)B_ * S_ * E_];        // concat heads

// ---------------------------------------------------------------------------
__device__ __forceinline__ uint32_t tfu(float f) {   // fp32 -> tf32 bits (rna)
    uint32_t u;
    asm("cvt.rna.tf32.f32 %0, %1;" : "=r"(u) : "f"(f));
    return u;
}
__device__ __forceinline__ uint32_t sptr(const void* p) {
    return (uint32_t)__cvta_generic_to_shared(p);
}
#define CP16(dst, src) \
    asm volatile("cp.async.cg.shared.global [%0], [%1], 16;" :: "r"(dst), "l"(src))
#define CP_COMMIT() asm volatile("cp.async.commit_group;")

__device__ __forceinline__ void mma8(float c[4], const uint32_t a[4], const uint32_t b[2]) {
    asm volatile("mma.sync.aligned.m16n8k8.row.col.f32.tf32.tf32.f32 "
        "{%0,%1,%2,%3}, {%4,%5,%6,%7}, {%8,%9}, {%0,%1,%2,%3};"
        : "+f"(c[0]), "+f"(c[1]), "+f"(c[2]), "+f"(c[3])
        : "r"(a[0]), "r"(a[1]), "r"(a[2]), "r"(a[3]), "r"(b[0]), "r"(b[1]));
}

// ---------------------------------------------------------------------------
// 128x128 tile GEMM, cp.async 2-stage pipeline: acc += A[128,Ktot] * op(B)
// TRANSB=1: Bp is [K,N] row-major (n contiguous) -> B smem [k][PB]
// TRANSB=0: Bp is [N,K] row-major (k contiguous) -> B smem [n][PA] (k-major)
// ---------------------------------------------------------------------------
template<int TRANSB>
__device__ __forceinline__ void gemm_tile(
    float acc[4][4][4],
    const float* __restrict__ A, int lda,
    const float* __restrict__ Bp, int ldb, int Ktot,
    float* sA, float* sB)
{
    const int ASTG = 128 * PA;
    const int BSTG = TRANSB ? BK * PB : 128 * PA;
    int tid = threadIdx.x, lane = tid & 31, wid = tid >> 5;
    int wm = (wid & 1) * 64, wn = (wid >> 1) * 32;

    auto issue = [&](int t, int buf) {
        int k0 = t * BK;
        #pragma unroll
        for (int i = 0; i < 2; i++) {
            int f = tid + i * 256;
            int row = f >> 2, q = f & 3;
            CP16(sptr(sA + buf * ASTG + row * PA + q * 4),
                 A + (size_t)row * lda + k0 + q * 4);
        }
        if (TRANSB == 1) {
            #pragma unroll
            for (int i = 0; i < 2; i++) {
                int f = tid + i * 256;
                int k = f >> 5, n4 = f & 31;
                CP16(sptr(sB + buf * BSTG + k * PB + n4 * 4),
                     Bp + (size_t)(k0 + k) * ldb + n4 * 4);
            }
        } else {
            #pragma unroll
            for (int i = 0; i < 2; i++) {
                int f = tid + i * 256;
                int n = f >> 2, q = f & 3;
                CP16(sptr(sB + buf * BSTG + n * PA + q * 4),
                     Bp + (size_t)n * ldb + k0 + q * 4);
            }
        }
        CP_COMMIT();
    };

    issue(0, 0);
    int T = Ktot / BK;
    for (int t = 0; t < T; t++) {
        if (t + 1 < T) {
            issue(t + 1, (t + 1) & 1);
            asm volatile("cp.async.wait_group 1;");
        } else {
            asm volatile("cp.async.wait_group 0;");
        }
        __syncthreads();
        const float* sAc = sA + (t & 1) * ASTG;
        const float* sBc = sB + (t & 1) * BSTG;
        #pragma unroll
        for (int ks = 0; ks < BK; ks += 8) {
            uint32_t a[4][4];
            #pragma unroll
            for (int mf = 0; mf < 4; mf++) {
                int r = wm + mf * 16 + (lane >> 2);
                int c = ks + (lane & 3);
                a[mf][0] = tfu(sAc[r * PA + c]);
                a[mf][1] = tfu(sAc[(r + 8) * PA + c]);
                a[mf][2] = tfu(sAc[r * PA + c + 4]);
                a[mf][3] = tfu(sAc[(r + 8) * PA + c + 4]);
            }
            uint32_t b[4][2];
            #pragma unroll
            for (int nf = 0; nf < 4; nf++) {
                int kk = ks + (lane & 3);
                int n  = wn + nf * 8 + (lane >> 2);
                if (TRANSB == 1) {
                    b[nf][0] = tfu(sBc[kk * PB + n]);
                    b[nf][1] = tfu(sBc[(kk + 4) * PB + n]);
                } else {
                    b[nf][0] = tfu(sBc[n * PA + kk]);
                    b[nf][1] = tfu(sBc[n * PA + kk + 4]);
                }
            }
            #pragma unroll
            for (int mf = 0; mf < 4; mf++)
                #pragma unroll
                for (int nf = 0; nf < 4; nf++)
                    mma8(acc[mf][nf], a[mf], b[nf]);
        }
        __syncthreads();
    }
}

// ---------------------------------------------------------------------------
// Kernel 1: projections  Out[b,h,s,d] = X[b,s,:] @ W[h,:,:]
// grid (2 nt, 64 mt, 9 = tensor*3 + head)
// ---------------------------------------------------------------------------
__global__ __launch_bounds__(256, 2) void proj_tc(
    const float* __restrict__ Xk, const float* __restrict__ Xv, const float* __restrict__ Xq,
    const float* __restrict__ WK, const float* __restrict__ WV, const float* __restrict__ WQ)
{
    __shared__ float sA[2 * 128 * PA];
    __shared__ float sB[2 * BK * PB];
    int z = blockIdx.z;
    int t = z / 3, h = z % 3;
    const float* X = (t == 0) ? Xk : (t == 1) ? Xv : Xq;
    const float* W = ((t == 0) ? WK : (t == 1) ? WV : WQ) + (size_t)h * E_ * D_;
    float* Out     = (t == 0) ? g_K : (t == 1) ? g_V : g_Q;

    int m0 = blockIdx.y * 128, n0 = blockIdx.x * 128;
    float acc[4][4][4] = {};
    gemm_tile<1>(acc, X + (size_t)m0 * E_, E_, W + n0, D_, E_, sA, sB);

    int lane = threadIdx.x & 31, wid = threadIdx.x >> 5;
    int wm = (wid & 1) * 64, wn = (wid >> 1) * 32;
    #pragma unroll
    for (int mf = 0; mf < 4; mf++) {
        #pragma unroll
        for (int half = 0; half < 2; half++) {
            int m = m0 + wm + mf * 16 + (lane >> 2) + half * 8;
            int bb = m >> 11, ss = m & (S_ - 1);
            float* orow = Out + (((size_t)(bb * H_ + h)) * S_ + ss) * D_ + n0;
            #pragma unroll
            for (int nf = 0; nf < 4; nf++) {
                int col = wn + nf * 8 + 2 * (lane & 3);
                float2 v = half ? make_float2(acc[mf][nf][2], acc[mf][nf][3])
                                : make_float2(acc[mf][nf][0], acc[mf][nf][1]);
                *(float2*)(orow + col) = v;
            }
        }
    }
}

// ---------------------------------------------------------------------------
// Kernel 2: scores  Sc[q,k] = Q[q,:].K[k,:] / sqrt(S)   (lower tiles only)
// grid (16 kt, 16 qt desc, 12 bh)
// ---------------------------------------------------------------------------
__global__ __launch_bounds__(256, 2) void scores_tc()
{
    int kt = blockIdx.x, qt = 15 - blockIdx.y, bh = blockIdx.z;
    if (kt > qt) return;
    __shared__ float sA[2 * 128 * PA];
    __shared__ float sB[2 * 128 * PA];

    int q0 = qt * 128, k0 = kt * 128;
    const float* Q = g_Q + (size_t)bh * S_ * D_ + (size_t)q0 * D_;
    const float* K = g_K + (size_t)bh * S_ * D_ + (size_t)k0 * D_;
    float acc[4][4][4] = {};
    gemm_tile<0>(acc, Q, D_, K, D_, D_, sA, sB);

    const float scale = 0.022097086912079612f;  // 1/sqrt(2048)
    int lane = threadIdx.x & 31, wid = threadIdx.x >> 5;
    int wm = (wid & 1) * 64, wn = (wid >> 1) * 32;
    float* Sc = g_Sc + (size_t)bh * S_ * S_;
    #pragma unroll
    for (int mf = 0; mf < 4; mf++) {
        #pragma unroll
        for (int half = 0; half < 2; half++) {
            int q = q0 + wm + mf * 16 + (lane >> 2) + half * 8;
            float* orow = Sc + (size_t)q * S_ + k0;
            #pragma unroll
            for (int nf = 0; nf < 4; nf++) {
                int col = wn + nf * 8 + 2 * (lane & 3);
                float2 v = half ? make_float2(acc[mf][nf][2] * scale, acc[mf][nf][3] * scale)
                                : make_float2(acc[mf][nf][0] * scale, acc[mf][nf][1] * scale);
                *(float2*)(orow + col) = v;
            }
        }
    }
}

// ---------------------------------------------------------------------------
// Kernel 3: causal softmax per row — register-resident single pass
// ---------------------------------------------------------------------------
__global__ __launch_bounds__(256) void softmax_kernel()
{
    int row = blockIdx.x;
    int q = row & (S_ - 1);
    float* p = g_Sc + (size_t)row * S_;
    int tid = threadIdx.x;

    float v[8];
    float m = -1e30f;
    #pragma unroll
    for (int i = 0; i < 8; i++) {
        int k = tid + i * 256;
        if (k <= q) { v[i] = p[k]; m = fmaxf(m, v[i]); }
    }
    #pragma unroll
    for (int o = 16; o; o >>= 1) m = fmaxf(m, __shfl_xor_sync(~0u, m, o));
    __shared__ float redm[8], reds[8];
    if ((tid & 31) == 0) redm[tid >> 5] = m;
    __syncthreads();
    if (tid < 32) {
        float t = (tid < 8) ? redm[tid] : -1e30f;
        #pragma unroll
        for (int o = 4; o; o >>= 1) t = fmaxf(t, __shfl_xor_sync(~0u, t, o));
        if (tid == 0) redm[0] = t;
    }
    __syncthreads();
    m = redm[0];

    float s = 0.f;
    #pragma unroll
    for (int i = 0; i < 8; i++) {
        int k = tid + i * 256;
        if (k <= q) { v[i] = __expf(v[i] - m); s += v[i]; }
    }
    #pragma unroll
    for (int o = 16; o; o >>= 1) s += __shfl_xor_sync(~0u, s, o);
    if ((tid & 31) == 0) reds[tid >> 5] = s;
    __syncthreads();
    if (tid < 32) {
        float t = (tid < 8) ? reds[tid] : 0.f;
        #pragma unroll
        for (int o = 4; o; o >>= 1) t += __shfl_xor_sync(~0u, t, o);
        if (tid == 0) reds[0] = t;
    }
    __syncthreads();
    float inv = 1.0f / reds[0];

    #pragma unroll
    for (int i = 0; i < 8; i++) {
        int k = tid + i * 256;
        if (k <= q) p[k] = v[i] * inv;
    }
    for (int k = q + 1 + tid; k < S_; k += 256) p[k] = 0.f;
}

// ---------------------------------------------------------------------------
// Kernel 4: Z = P @ V  -> concat layout g_C[b, q, h*D+d]
// grid (2 nt, 16 qt desc, 12 bh); K truncated at diagonal (P zero beyond)
// ---------------------------------------------------------------------------
__global__ __launch_bounds__(256, 2) void pv_tc()
{
    int nt = blockIdx.x, qt = 15 - blockIdx.y, bh = blockIdx.z;
    __shared__ float sA[2 * 128 * PA];
    __shared__ float sB[2 * BK * PB];

    int q0 = qt * 128, n0 = nt * 128;
    const float* P = g_Sc + (size_t)bh * S_ * S_ + (size_t)q0 * S_;
    const float* V = g_V + (size_t)bh * S_ * D_ + n0;
    float acc[4][4][4] = {};
    gemm_tile<1>(acc, P, S_, V, D_, (qt + 1) * 128, sA, sB);

    int lane = threadIdx.x & 31, wid = threadIdx.x >> 5;
    int wm = (wid & 1) * 64, wn = (wid >> 1) * 32;
    int bb = bh / H_, h = bh - bb * H_;
    #pragma unroll
    for (int mf = 0; mf < 4; mf++) {
        #pragma unroll
        for (int half = 0; half < 2; half++) {
            int q = q0 + wm + mf * 16 + (lane >> 2) + half * 8;
            float* orow = g_C + ((size_t)(bb * S_ + q)) * E_ + h * D_ + n0;
            #pragma unroll
            for (int nf = 0; nf < 4; nf++) {
                int col = wn + nf * 8 + 2 * (lane & 3);
                float2 v = half ? make_float2(acc[mf][nf][2], acc[mf][nf][3])
                                : make_float2(acc[mf][nf][0], acc[mf][nf][1]);
                *(float2*)(orow + col) = v;
            }
        }
    }
}

// ---------------------------------------------------------------------------
// Kernel 5: Out = g_C @ Wo + bo   grid (6 nt, 64 mt)
// ---------------------------------------------------------------------------
__global__ __launch_bounds__(256, 2) void out_tc(
    const float* __restrict__ Wo, const float* __restrict__ bo, float* __restrict__ Out)
{
    __shared__ float sA[2 * 128 * PA];
    __shared__ float sB[2 * BK * PB];
    int n0 = blockIdx.x * 128, m0 = blockIdx.y * 128;
    float acc[4][4][4] = {};
    gemm_tile<1>(acc, g_C + (size_t)m0 * E_, E_, Wo + n0, E_, E_, sA, sB);

    int lane = threadIdx.x & 31, wid = threadIdx.x >> 5;
    int wm = (wid & 1) * 64, wn = (wid >> 1) * 32;
    #pragma unroll
    for (int mf = 0; mf < 4; mf++) {
        #pragma unroll
        for (int half = 0; half < 2; half++) {
            int m = m0 + wm + mf * 16 + (lane >> 2) + half * 8;
            float* orow = Out + (size_t)m * E_ + n0;
            #pragma unroll
            for (int nf = 0; nf < 4; nf++) {
                int col = wn + nf * 8 + 2 * (lane & 3);
                float2 bv = *(const float2*)(bo + n0 + col);
                float2 v = half ? make_float2(acc[mf][nf][2] + bv.x, acc[mf][nf][3] + bv.y)
                                : make_float2(acc[mf][nf][0] + bv.x, acc[mf][nf][1] + bv.y);
                *(float2*)(orow + col) = v;
            }
        }
    }
}

// ---------------------------------------------------------------------------
extern "C" void kernel_launch(void* const* d_in, const int* in_sizes, int n_in,
                              void* d_out, int out_size)
{
    const float* Xk = (const float*)d_in[0];
    const float* Xv = (const float*)d_in[1];
    const float* Xq = (const float*)d_in[2];
    const float* WK = (const float*)d_in[3];
    const float* WV = (const float*)d_in[4];
    const float* WQ = (const float*)d_in[5];
    const float* Wo = (const float*)d_in[6];
    const float* bo = (const float*)d_in[7];
    float* out = (float*)d_out;

    proj_tc<<<dim3(2, 64, 9), 256>>>(Xk, Xv, Xq, WK, WV, WQ);
    scores_tc<<<dim3(16, 16, 12), 256>>>();
    softmax_kernel<<<dim3(B_ * H_ * S_), 256>>>();
    pv_tc<<<dim3(2, 16, 12), 256>>>();
    out_tc<<<dim3(6, 64), 256>>>(Wo, bo, out);
}